// round 4
// baseline (speedup 1.0000x reference)
#include <cuda_runtime.h>
#include <cuda_bf16.h>
#include <cstdint>
#include <cstddef>

// ---------------- problem constants ----------------
#define TQ 512
#define HQ 1024
#define VQ 128000
#define NTOK 2048          // B*T
#define MT 128             // M tile (tokens)
#define NT 128             // N tile (vocab)
#define KC 64              // K chunk (bf16 elems) = 128 bytes/row
#define NKC 16             // 1024 / 64
#define NTILES_M 16        // 2048 / 128
#define NTILES_N 1000      // 128000 / 128

// ---------------- scratch (no allocations allowed) ----------------
__device__ __nv_bfloat16 g_Wbf[(size_t)VQ * HQ];   // 256 MB bf16 copy of W
__device__ __nv_bfloat16 g_xbf[(size_t)NTOK * HQ]; // 4 MB bf16 copy of x
__device__ float g_part[(size_t)NTOK * NTILES_N];  // partial sum-exp per (token, N-tile)
__device__ float g_tgt[NTOK];                      // exact capped target logit
__device__ float g_logp[NTOK];                     // per-token log-prob

// ---------------- PTX helpers (base sm_100 compatible ONLY) ----------------
__device__ __forceinline__ uint32_t smem_u32(const void* p) {
    uint32_t a;
    asm("{ .reg .u64 t; cvta.to.shared.u64 t, %1; cvt.u32.u64 %0, t; }" : "=r"(a) : "l"(p));
    return a;
}
__device__ __forceinline__ void cpasync16(uint32_t dst, const void* src) {
    asm volatile("cp.async.cg.shared.global [%0], [%1], 16;" :: "r"(dst), "l"(src));
}
#define CP_COMMIT() asm volatile("cp.async.commit_group;" ::: "memory")
#define CP_WAIT1()  asm volatile("cp.async.wait_group 1;" ::: "memory")

__device__ __forceinline__ void ldsm4(uint32_t* r, uint32_t addr) {
    asm volatile("ldmatrix.sync.aligned.m8n8.x4.shared.b16 {%0,%1,%2,%3}, [%4];"
        : "=r"(r[0]), "=r"(r[1]), "=r"(r[2]), "=r"(r[3]) : "r"(addr));
}
__device__ __forceinline__ void mma16816(float* c, const uint32_t* a, const uint32_t* b) {
    asm volatile("mma.sync.aligned.m16n8k16.row.col.f32.bf16.bf16.f32 "
        "{%0,%1,%2,%3}, {%4,%5,%6,%7}, {%8,%9}, {%0,%1,%2,%3};"
        : "+f"(c[0]), "+f"(c[1]), "+f"(c[2]), "+f"(c[3])
        : "r"(a[0]), "r"(a[1]), "r"(a[2]), "r"(a[3]), "r"(b[0]), "r"(b[1]));
}

#define SW128(o) ((o) ^ (((o) >> 3) & 0x70))

// ---------------- SMEM layout ----------------
// per stage: A tile 128x64 bf16 (16KB) + B tile 128x64 bf16 (16KB) = 32KB; 2 stages.
#define A_BYTES    16384
#define STAGE_B    32768
#define SMEM_BYTES (2 * STAGE_B)

// ---------------- conversion kernels ----------------
__global__ void convX_kernel(const float* __restrict__ x) {
    const size_t n4 = (size_t)NTOK * HQ / 4;
    for (size_t i = blockIdx.x * blockDim.x + threadIdx.x; i < n4;
         i += (size_t)gridDim.x * blockDim.x) {
        float4 v = reinterpret_cast<const float4*>(x)[i];
        __nv_bfloat162 a, b;
        a.x = __float2bfloat16_rn(v.x); a.y = __float2bfloat16_rn(v.y);
        b.x = __float2bfloat16_rn(v.z); b.y = __float2bfloat16_rn(v.w);
        reinterpret_cast<__nv_bfloat162*>(g_xbf)[2 * i]     = a;
        reinterpret_cast<__nv_bfloat162*>(g_xbf)[2 * i + 1] = b;
    }
}
__global__ void convW_kernel(const float* __restrict__ W) {
    const size_t n4 = (size_t)VQ * HQ / 4;
    for (size_t i = blockIdx.x * blockDim.x + threadIdx.x; i < n4;
         i += (size_t)gridDim.x * blockDim.x) {
        float4 v = reinterpret_cast<const float4*>(W)[i];
        __nv_bfloat162 a, b;
        a.x = __float2bfloat16_rn(v.x); a.y = __float2bfloat16_rn(v.y);
        b.x = __float2bfloat16_rn(v.z); b.y = __float2bfloat16_rn(v.w);
        reinterpret_cast<__nv_bfloat162*>(g_Wbf)[2 * i]     = a;
        reinterpret_cast<__nv_bfloat162*>(g_Wbf)[2 * i + 1] = b;
    }
}

// ---------------- softcap helper ----------------
__device__ __forceinline__ float softcap(float l) {
    float u = l * l * (1.0f / 900.0f);
    // 30*tanh(l/30): even polynomial, |err| < 1e-5 for |l| <= 15
    float c = l * (1.0f - u * (0.33333334f - u * (0.13333334f
                  - u * (0.053968254f - u * 0.021869489f))));
    if (fabsf(l) > 15.f) c = 30.f * tanhf(l * (1.f / 30.f));
    return c;
}

// ---------------- GEMM + fused sum-exp epilogue ----------------
__global__ void __launch_bounds__(256) gemm_lse_kernel() {
    extern __shared__ char smem[];
    const uint32_t sb = smem_u32(smem);
    const int tid  = threadIdx.x;
    const int lane = tid & 31;
    const int wid  = tid >> 5;
    const int warp_m = wid >> 2;       // 0..1 (64 rows each)
    const int warp_n = wid & 3;        // 0..3 (32 cols each)
    const int tile_m = blockIdx.x;
    const int tile_n = blockIdx.y;

    const __nv_bfloat16* xg = g_xbf + (size_t)tile_m * MT * HQ;
    const __nv_bfloat16* wg = g_Wbf + (size_t)tile_n * NT * HQ;

    // ---- cp.async tile loader ----
    // One K-chunk row = KC*2 = 128 bytes = 8 chunks of 16B.
    // Per operand: 128 rows * 8 chunks = 1024 cp.asyncs = 4 iters x 256 threads.
    auto prefetch = [&](int c, int stage) {
        const int ko = c * KC;
        uint32_t base = sb + stage * STAGE_B;
        #pragma unroll
        for (int i = 0; i < 4; ++i) {
            int idx = tid + 256 * i;           // 0..1023
            int row = idx >> 3, ch = idx & 7;  // 128 rows x 8 chunks
            uint32_t off = (uint32_t)(row * 128 + ch * 16);
            cpasync16(base + SW128(off), xg + (size_t)row * HQ + ko + ch * 8);
        }
        #pragma unroll
        for (int i = 0; i < 4; ++i) {
            int idx = tid + 256 * i;
            int row = idx >> 3, ch = idx & 7;
            uint32_t off = (uint32_t)(row * 128 + ch * 16);
            cpasync16(base + A_BYTES + SW128(off), wg + (size_t)row * HQ + ko + ch * 8);
        }
    };

    float acc[4][4][4];
    #pragma unroll
    for (int mi = 0; mi < 4; ++mi)
        #pragma unroll
        for (int ni = 0; ni < 4; ++ni)
            #pragma unroll
            for (int j = 0; j < 4; ++j) acc[mi][ni][j] = 0.f;

    prefetch(0, 0); CP_COMMIT();
    prefetch(1, 1); CP_COMMIT();

    // ldmatrix lane-address components (canonical x4 fragment layouts)
    const int a_row = ((lane >> 3) & 1) * 8 + (lane & 7); // matrix row within 16
    const int a_kc  = (lane >> 4);                         // 0/1: k halves
    const int b_row = (lane & 7) + ((lane >> 4) << 3);     // n within 16
    const int b_kc  = ((lane >> 3) & 1);                   // 0/1: k halves

    for (int c = 0; c < NKC; ++c) {
        CP_WAIT1();
        __syncthreads();
        const int stage = c & 1;
        const uint32_t sA = sb + stage * STAGE_B;
        const uint32_t sB = sA + A_BYTES;

        #pragma unroll
        for (int ks = 0; ks < 4; ++ks) {
            uint32_t a[4][4];
            #pragma unroll
            for (int mi = 0; mi < 4; ++mi) {
                uint32_t off = (uint32_t)((warp_m * 64 + mi * 16 + a_row) * 128
                                          + (ks * 2 + a_kc) * 16);
                ldsm4(a[mi], sA + SW128(off));
            }
            uint32_t b[4][2];
            #pragma unroll
            for (int p = 0; p < 2; ++p) {
                uint32_t off = (uint32_t)((warp_n * 32 + p * 16 + b_row) * 128
                                          + (ks * 2 + b_kc) * 16);
                uint32_t r[4];
                ldsm4(r, sB + SW128(off));
                b[p * 2 + 0][0] = r[0]; b[p * 2 + 0][1] = r[1];
                b[p * 2 + 1][0] = r[2]; b[p * 2 + 1][1] = r[3];
            }
            #pragma unroll
            for (int mi = 0; mi < 4; ++mi)
                #pragma unroll
                for (int ni = 0; ni < 4; ++ni)
                    mma16816(acc[mi][ni], a[mi], b[ni]);
        }
        __syncthreads();
        if (c + 2 < NKC) prefetch(c + 2, stage);
        CP_COMMIT();
    }

    // ---- epilogue: softcap + exp, reduce over this CTA's 128 vocab cols ----
    float* sums = reinterpret_cast<float*>(smem);   // [4 warp_n][128 rows]
    __syncthreads();

    #pragma unroll
    for (int mi = 0; mi < 4; ++mi) {
        float s0 = 0.f, s1 = 0.f;
        #pragma unroll
        for (int ni = 0; ni < 4; ++ni) {
            s0 += __expf(softcap(acc[mi][ni][0])) + __expf(softcap(acc[mi][ni][1]));
            s1 += __expf(softcap(acc[mi][ni][2])) + __expf(softcap(acc[mi][ni][3]));
        }
        // reduce across the 4 lanes sharing the same rows (lane%4 = col groups)
        #pragma unroll
        for (int o = 1; o <= 2; o <<= 1) {
            s0 += __shfl_xor_sync(0xFFFFFFFFu, s0, o);
            s1 += __shfl_xor_sync(0xFFFFFFFFu, s1, o);
        }
        if ((lane & 3) == 0) {
            int r = warp_m * 64 + mi * 16 + (lane >> 2);
            sums[warp_n * 128 + r]     = s0;
            sums[warp_n * 128 + r + 8] = s1;
        }
    }
    __syncthreads();
    if (tid < 128) {
        float t = sums[tid] + sums[128 + tid] + sums[256 + tid] + sums[384 + tid];
        g_part[((size_t)tile_m * MT + tid) * NTILES_N + tile_n] = t;
    }
}

// ---------------- exact fp32 target logit (target is int32) ----------------
__global__ void __launch_bounds__(128) tgt_kernel(const float* __restrict__ x,
                                                  const float* __restrict__ W,
                                                  const int* __restrict__ tg) {
    const int t = blockIdx.x;
    const int tid = threadIdx.x;
    int tv = tg[t];
    int lab = tv < 0 ? 0 : tv;
    if (lab >= VQ) lab = VQ - 1;   // defensive clamp: never fault
    const float4* xr = reinterpret_cast<const float4*>(x + (size_t)t * HQ);
    const float4* wr = reinterpret_cast<const float4*>(W + (size_t)lab * HQ);
    float s = 0.f;
    #pragma unroll
    for (int i = tid; i < HQ / 4; i += 128) {
        float4 a = xr[i], b = wr[i];
        s += a.x * b.x + a.y * b.y + a.z * b.z + a.w * b.w;
    }
    #pragma unroll
    for (int o = 16; o; o >>= 1) s += __shfl_xor_sync(0xFFFFFFFFu, s, o);
    __shared__ float ws[4];
    if ((tid & 31) == 0) ws[tid >> 5] = s;
    __syncthreads();
    if (tid == 0) {
        float d = ws[0] + ws[1] + ws[2] + ws[3];
        g_tgt[t] = 30.0f * tanhf(d * (1.0f / 30.0f));
    }
}

// ---------------- per-token reduce: logp = capped_tgt - log(sum_exp) ----------------
__global__ void lse_kernel() {
    const int t = blockIdx.x;
    const int l = threadIdx.x;
    const float* p = g_part + (size_t)t * NTILES_N;
    float s = 0.f;
    for (int i = l; i < NTILES_N; i += 128) s += p[i];
    #pragma unroll
    for (int o = 16; o; o >>= 1) s += __shfl_xor_sync(0xFFFFFFFFu, s, o);
    __shared__ float ws[4];
    if ((l & 31) == 0) ws[l >> 5] = s;
    __syncthreads();
    if (l == 0) {
        float tot = ws[0] + ws[1] + ws[2] + ws[3];
        g_logp[t] = g_tgt[t] - logf(tot);
    }
}

// ---------------- final loss (deterministic single-warp reduction) ----------------
__global__ void loss_kernel(const int* __restrict__ tg, float* __restrict__ out) {
    const int l = threadIdx.x;
    float avg[4];
    #pragma unroll
    for (int b = 0; b < 4; ++b) {
        float s = 0.f, c = 0.f;
        for (int i = l; i < TQ; i += 32) {
            int idx = b * TQ + i;
            if (tg[idx] != -100) { s += g_logp[idx]; c += 1.f; }
        }
        #pragma unroll
        for (int o = 16; o; o >>= 1) {
            s += __shfl_xor_sync(0xFFFFFFFFu, s, o);
            c += __shfl_xor_sync(0xFFFFFFFFu, c, o);
        }
        avg[b] = s / c;
    }
    if (l == 0)
        out[0] = -0.1f * 0.5f * ((avg[0] - avg[2]) + (avg[1] - avg[3]));
}

// ---------------- launch ----------------
extern "C" void kernel_launch(void* const* d_in, const int* in_sizes, int n_in,
                              void* d_out, int out_size) {
    const float* x = (const float*)d_in[0];
    const float* W = (const float*)d_in[1];
    const int* tg = (const int*)d_in[2];
    float* out = (float*)d_out;

    cudaFuncSetAttribute(gemm_lse_kernel,
                         cudaFuncAttributeMaxDynamicSharedMemorySize, SMEM_BYTES);

    convX_kernel<<<64, 256>>>(x);
    convW_kernel<<<2048, 256>>>(W);
    gemm_lse_kernel<<<dim3(NTILES_M, NTILES_N), 256, SMEM_BYTES>>>();
    tgt_kernel<<<NTOK, 128>>>(x, W, tg);
    lse_kernel<<<NTOK, 128>>>();
    loss_kernel<<<1, 32>>>(tg, out);
}